// round 10
// baseline (speedup 1.0000x reference)
#include <cuda_runtime.h>
#include <cuda_bf16.h>
#include <math.h>
#include <stdint.h>

#define D 512
#define MROWS (96*1369)   // 131424
#define NEWBN 192

// ---------------- scratch (device globals: allocation-free rule) ----------------
__device__ __nv_bfloat16 g_fH[(size_t)MROWS * D], g_fL[(size_t)MROWS * D];
__device__ __nv_bfloat16 g_t1H[(size_t)MROWS * D], g_t1L[(size_t)MROWS * D];
__device__ __nv_bfloat16 g_t2H[(size_t)MROWS * D], g_t2L[(size_t)MROWS * D];
__device__ __nv_bfloat16 g_x3H[(size_t)MROWS * D], g_x3L[(size_t)MROWS * D];
__device__ __nv_bfloat16 g_wH[6 * D * D], g_wL[6 * D * D];   // same layout as W: [l][k][n]
__device__ float g_pooled[96 * D];
__device__ float g_gctx[32 * D];
__device__ float g_s1[96 * D];
__device__ float g_s2[32 * D];
__device__ float g_tf[96 * D];
__device__ float g_allf[NEWBN * D];
__device__ float g_s3[NEWBN * D];
__device__ float g_s4[NEWBN * D];
__device__ float g_t[NEWBN * 3];
__device__ float g_r[NEWBN * 9];

// ---------------- PTX helpers (baseline ISA only: sm_80/75 features) ----------------
__device__ __forceinline__ uint32_t smem_u32(const void* p) {
    uint32_t a;
    asm("{ .reg .u64 t; cvta.to.shared.u64 t, %1; cvt.u32.u64 %0, t; }" : "=r"(a) : "l"(p));
    return a;
}

#define CPA16(dst, src, sz) asm volatile("cp.async.cg.shared.global [%0], [%1], 16, %2;" :: "r"(dst), "l"(src), "r"(sz) : "memory")
#define CP_COMMIT() asm volatile("cp.async.commit_group;" ::: "memory")
#define CP_WAIT2()  asm volatile("cp.async.wait_group 2;" ::: "memory")

__device__ __forceinline__ void ldsm_x4(uint32_t& r0, uint32_t& r1, uint32_t& r2, uint32_t& r3, uint32_t a) {
    asm volatile("ldmatrix.sync.aligned.m8n8.x4.shared.b16 {%0,%1,%2,%3}, [%4];"
                 : "=r"(r0), "=r"(r1), "=r"(r2), "=r"(r3) : "r"(a));
}
__device__ __forceinline__ void ldsm_x4t(uint32_t& r0, uint32_t& r1, uint32_t& r2, uint32_t& r3, uint32_t a) {
    asm volatile("ldmatrix.sync.aligned.m8n8.x4.trans.shared.b16 {%0,%1,%2,%3}, [%4];"
                 : "=r"(r0), "=r"(r1), "=r"(r2), "=r"(r3) : "r"(a));
}
__device__ __forceinline__ void mma_bf16(float* c, const uint32_t* a, const uint32_t* b) {
    asm volatile("mma.sync.aligned.m16n8k16.row.col.f32.bf16.bf16.f32 "
                 "{%0,%1,%2,%3}, {%4,%5,%6,%7}, {%8,%9}, {%0,%1,%2,%3};"
                 : "+f"(c[0]), "+f"(c[1]), "+f"(c[2]), "+f"(c[3])
                 : "r"(a[0]), "r"(a[1]), "r"(a[2]), "r"(a[3]), "r"(b[0]), "r"(b[1]));
}

// ---------------- smem layout: BK=64 stages ----------------
#define ASTRIDE 72          // bf16 elems per A row (64 + 8 pad) -> 144B, bank phase ok
#define BSTRIDE 136         // bf16 elems per B k-row (128 + 8 pad) -> 272B, bank phase ok
#define A_BYTES (128 * ASTRIDE * 2)   // 18432
#define B_BYTES (64 * BSTRIDE * 2)    // 17408
#define STAGE_B (A_BYTES + B_BYTES)   // 35840
#define NBUF 4
#define SMEM_TOTAL (NBUF * STAGE_B)   // 143360
#define NST 24             // 3 passes x 8 stages (BK=64, K=512)

// ---------------- mma.sync GEMM: out = [res +] relu(A @ W + bias), hi/lo split ----------------
// Effective: (AH+AL) @ (WH+WL) ~= AH@WH + AL@WH + AH@WL, K=3*512 loop, fp32 accum.
__global__ __launch_bounds__(256)
void gemm_mma(const __nv_bfloat16* __restrict__ AH, const __nv_bfloat16* __restrict__ AL,
              const __nv_bfloat16* __restrict__ BH, const __nv_bfloat16* __restrict__ BL,
              const float* __restrict__ bias,
              const float* __restrict__ resF,
              const __nv_bfloat16* __restrict__ resH, const __nv_bfloat16* __restrict__ resL,
              __nv_bfloat16* __restrict__ outH, __nv_bfloat16* __restrict__ outL,
              int M)
{
    extern __shared__ char smem[];
    const uint32_t sb = smem_u32(smem);
    const int tid = threadIdx.x;
    const int wid = tid >> 5, lane = tid & 31;
    const int bm = blockIdx.y * 128;
    const int nb = blockIdx.x * 128;
    const int wm = (wid & 1) * 64;    // warp row base in tile
    const int wn = (wid >> 1) * 32;   // warp col base in tile

    float acc[4][4][4];
#pragma unroll
    for (int i = 0; i < 4; i++)
#pragma unroll
        for (int j = 0; j < 4; j++)
#pragma unroll
            for (int k = 0; k < 4; k++) acc[i][j][k] = 0.f;

    // stage loader: 8 x 16B cp.async per thread (A: 1024 chunks, B: 1024 chunks)
    auto load_stage = [&](int gs, int buf) {
        const int p = gs >> 3;             // pass 0: AH*BH, 1: AL*BH, 2: AH*BL
        const int kc = (gs & 7) * 64;
        const __nv_bfloat16* Asrc = (p == 1) ? AL : AH;
        const __nv_bfloat16* Bsrc = (p == 2) ? BL : BH;
        const uint32_t base = sb + buf * STAGE_B;
        // A: 128 rows x 64k = 1024 x 16B chunks
#pragma unroll
        for (int i = 0; i < 4; i++) {
            int c = tid + 256 * i;
            int m = c >> 3, kk = c & 7;
            int row = bm + m;
            int sz = (row < M) ? 16 : 0;
            int rc = (row < M) ? row : 0;
            const __nv_bfloat16* s = Asrc + (size_t)rc * D + kc + kk * 8;
            CPA16(base + (uint32_t)(m * ASTRIDE + kk * 8) * 2, s, sz);
        }
        // B: 64 k-rows x 128n = 1024 x 16B chunks
#pragma unroll
        for (int i = 0; i < 4; i++) {
            int c = tid + 256 * i;
            int k = c >> 4, nn = c & 15;
            const __nv_bfloat16* s = Bsrc + (size_t)(kc + k) * D + nb + nn * 8;
            CPA16(base + A_BYTES + (uint32_t)(k * BSTRIDE + nn * 8) * 2, s, 16);
        }
    };

    load_stage(0, 0); CP_COMMIT();
    load_stage(1, 1); CP_COMMIT();
    load_stage(2, 2); CP_COMMIT();

    const int lrow = lane & 15;        // ldmatrix row within 16
    const int lcol = (lane >> 4) * 8;  // ldmatrix col-half

    for (int s = 0; s < NST; s++) {
        CP_WAIT2();
        __syncthreads();
        // Safe: slot (s+3)&3 == slot (s-1)&3; all stage s-1 reads completed
        // before the barrier above, so the overwrite cannot race.
        if (s + 3 < NST) load_stage(s + 3, (s + 3) & 3);
        CP_COMMIT();

        const uint32_t aBase = sb + (s & 3) * STAGE_B;
        const uint32_t bBase = aBase + A_BYTES;
#pragma unroll
        for (int ks = 0; ks < 64; ks += 16) {
            uint32_t a[4][4], b[4][2];
#pragma unroll
            for (int mf = 0; mf < 4; mf++) {
                uint32_t addr = aBase + (uint32_t)((wm + mf * 16 + lrow) * ASTRIDE + ks + lcol) * 2;
                ldsm_x4(a[mf][0], a[mf][1], a[mf][2], a[mf][3], addr);
            }
#pragma unroll
            for (int ng = 0; ng < 2; ng++) {
                uint32_t addr = bBase + (uint32_t)((ks + lrow) * BSTRIDE + wn + ng * 16 + lcol) * 2;
                ldsm_x4t(b[ng * 2][0], b[ng * 2][1], b[ng * 2 + 1][0], b[ng * 2 + 1][1], addr);
            }
#pragma unroll
            for (int mf = 0; mf < 4; mf++)
#pragma unroll
                for (int nf = 0; nf < 4; nf++)
                    mma_bf16(acc[mf][nf], a[mf], b[nf]);
        }
    }

    // ---- epilogue: bias + relu + residual, split-write bf16 hi/lo ----
    const int qr = lane >> 2;          // row within 8
    const int qc = (lane & 3) * 2;     // col pair
#pragma unroll
    for (int mf = 0; mf < 4; mf++) {
#pragma unroll
        for (int half = 0; half < 2; half++) {
            int row = bm + wm + mf * 16 + qr + half * 8;
            if (row >= M) continue;
#pragma unroll
            for (int nf = 0; nf < 4; nf++) {
                int col = nb + wn + nf * 8 + qc;
                float v0 = acc[mf][nf][half * 2 + 0] + bias[col];
                float v1 = acc[mf][nf][half * 2 + 1] + bias[col + 1];
                v0 = fmaxf(v0, 0.f);
                v1 = fmaxf(v1, 0.f);
                size_t base = (size_t)row * D + col;
                if (resF) {
                    v0 += resF[base];
                    v1 += resF[base + 1];
                } else if (resH) {
                    v0 += __bfloat162float(resH[base]) + __bfloat162float(resL[base]);
                    v1 += __bfloat162float(resH[base + 1]) + __bfloat162float(resL[base + 1]);
                }
                __nv_bfloat16 h0 = __float2bfloat16(v0);
                __nv_bfloat16 h1 = __float2bfloat16(v1);
                __nv_bfloat16 l0 = __float2bfloat16(v0 - __bfloat162float(h0));
                __nv_bfloat16 l1 = __float2bfloat16(v1 - __bfloat162float(h1));
                *reinterpret_cast<__nv_bfloat162*>(outH + base) = __halves2bfloat162(h0, h1);
                *reinterpret_cast<__nv_bfloat162*>(outL + base) = __halves2bfloat162(l0, l1);
            }
        }
    }
}

// ---------------- fp32 -> bf16 hi/lo split ----------------
__global__ void split_kernel(const float4* __restrict__ x,
                             __nv_bfloat162* __restrict__ h, __nv_bfloat162* __restrict__ l,
                             size_t n4)
{
    size_t i = (size_t)blockIdx.x * blockDim.x + threadIdx.x;
    size_t stride = (size_t)gridDim.x * blockDim.x;
    for (; i < n4; i += stride) {
        float4 v = x[i];
        __nv_bfloat16 h0 = __float2bfloat16(v.x), h1 = __float2bfloat16(v.y);
        __nv_bfloat16 h2 = __float2bfloat16(v.z), h3 = __float2bfloat16(v.w);
        h[2 * i]     = __halves2bfloat162(h0, h1);
        h[2 * i + 1] = __halves2bfloat162(h2, h3);
        l[2 * i]     = __halves2bfloat162(__float2bfloat16(v.x - __bfloat162float(h0)),
                                          __float2bfloat16(v.y - __bfloat162float(h1)));
        l[2 * i + 1] = __halves2bfloat162(__float2bfloat16(v.z - __bfloat162float(h2)),
                                          __float2bfloat16(v.w - __bfloat162float(h3)));
    }
}

// ---------------- weight split (same [l][k][n] layout) ----------------
__global__ void wprep_kernel(const float* __restrict__ W,
                             __nv_bfloat16* __restrict__ WH, __nv_bfloat16* __restrict__ WL)
{
    int idx = blockIdx.x * blockDim.x + threadIdx.x;   // < 6*512*512
    float v = W[idx];
    __nv_bfloat16 h = __float2bfloat16(v);
    WH[idx] = h;
    WL[idx] = __float2bfloat16(v - __bfloat162float(h));
}

// ---------------- mean over hw (1369): parallel partial sums + atomics ----------------
__global__ void pool_zero(float* __restrict__ pooled)
{
    pooled[blockIdx.x * blockDim.x + threadIdx.x] = 0.f;
}

__global__ void pool_atomic(const __nv_bfloat16* __restrict__ xh,
                            const __nv_bfloat16* __restrict__ xl, float* __restrict__ out)
{
    int bn = blockIdx.x;
    int chunk = blockIdx.y;
    int d = threadIdx.x;
    int r0 = chunk * 172;
    int r1 = r0 + 172; if (r1 > 1369) r1 = 1369;
    const __nv_bfloat16* ph = xh + (size_t)bn * 1369 * D + (size_t)r0 * D + d;
    const __nv_bfloat16* pl = xl + (size_t)bn * 1369 * D + (size_t)r0 * D + d;
    float s = 0.f;
    for (int i = 0; i < r1 - r0; i++)
        s += __bfloat162float(ph[(size_t)i * D]) + __bfloat162float(pl[(size_t)i * D]);
    atomicAdd(&out[bn * D + d], s * (1.0f / 1369.0f));
}

// ---------------- mean over N=3 frames ----------------
__global__ void gctx_kernel(const float* __restrict__ pooled, float* __restrict__ out)
{
    int b = blockIdx.x;
    int d = threadIdx.x;
    float s = pooled[(b * 3 + 0) * D + d] + pooled[(b * 3 + 1) * D + d] + pooled[(b * 3 + 2) * D + d];
    out[b * D + d] = s * (1.0f / 3.0f);
}

// ---------------- small GEMM: C[m,n] = act(A[m,:] @ W[:,n] + bias[n]), K=512 ----------------
__global__ void small_gemm(const float* __restrict__ A, const float* __restrict__ W,
                           const float* __restrict__ bias, float* __restrict__ C,
                           int N, int doRelu)
{
    int n = blockIdx.x * blockDim.x + threadIdx.x;
    int m = blockIdx.y;
    if (n >= N) return;
    const float* a = A + (size_t)m * D;
    const float* w = W + n;
    float s0 = 0.f, s1 = 0.f, s2 = 0.f, s3 = 0.f;
#pragma unroll 4
    for (int k = 0; k < D; k += 4) {
        s0 = fmaf(a[k + 0], w[(size_t)(k + 0) * N], s0);
        s1 = fmaf(a[k + 1], w[(size_t)(k + 1) * N], s1);
        s2 = fmaf(a[k + 2], w[(size_t)(k + 2) * N], s2);
        s3 = fmaf(a[k + 3], w[(size_t)(k + 3) * N], s3);
    }
    float s = ((s0 + s1) + (s2 + s3)) + bias[n];
    if (doRelu) s = fmaxf(s, 0.f);
    C[(size_t)m * N + n] = s;
}

// ---------------- special Procrustes SVD (3x3) + pose assembly ----------------
__device__ __forceinline__ void jrot(double H[3][3], double V[3][3], int p, int q)
{
    double apq = H[p][q];
    if (fabs(apq) < 1e-300) return;
    double theta = (H[q][q] - H[p][p]) / (2.0 * apq);
    double t = ((theta >= 0.0) ? 1.0 : -1.0) / (fabs(theta) + sqrt(theta * theta + 1.0));
    double c = 1.0 / sqrt(t * t + 1.0);
    double sn = t * c;
#pragma unroll
    for (int k = 0; k < 3; k++) {
        double hkp = H[k][p], hkq = H[k][q];
        H[k][p] = c * hkp - sn * hkq;
        H[k][q] = sn * hkp + c * hkq;
    }
#pragma unroll
    for (int k = 0; k < 3; k++) {
        double hpk = H[p][k], hqk = H[q][k];
        H[p][k] = c * hpk - sn * hqk;
        H[q][k] = sn * hpk + c * hqk;
    }
#pragma unroll
    for (int k = 0; k < 3; k++) {
        double vkp = V[k][p], vkq = V[k][q];
        V[k][p] = c * vkp - sn * vkq;
        V[k][q] = sn * vkp + c * vkq;
    }
}

__global__ void pose_svd_kernel(const float* __restrict__ tvec,
                                const float* __restrict__ rmat,
                                float* __restrict__ out)
{
    int i = blockIdx.x * blockDim.x + threadIdx.x;
    if (i >= NEWBN) return;

    double B[3][3];
#pragma unroll
    for (int r = 0; r < 3; r++) {
        double a0 = (double)rmat[i * 9 + r * 3 + 0];
        double a1 = (double)rmat[i * 9 + r * 3 + 1];
        double a2 = (double)rmat[i * 9 + r * 3 + 2];
        double nrm = sqrt(a0 * a0 + a1 * a1 + a2 * a2);
        nrm = fmax(nrm, 1e-12);
        B[r][0] = a0 / nrm; B[r][1] = a1 / nrm; B[r][2] = a2 / nrm;
    }
    double H[3][3];
#pragma unroll
    for (int r = 0; r < 3; r++)
#pragma unroll
        for (int c = 0; c < 3; c++)
            H[r][c] = B[0][r] * B[0][c] + B[1][r] * B[1][c] + B[2][r] * B[2][c];

    double V[3][3] = {{1,0,0},{0,1,0},{0,0,1}};
    for (int sweep = 0; sweep < 15; sweep++) {
        jrot(H, V, 0, 1);
        jrot(H, V, 0, 2);
        jrot(H, V, 1, 2);
    }
    double l0 = H[0][0], l1 = H[1][1], l2 = H[2][2];
    int i0 = 0, i1 = 1, i2 = 2;
    if (l0 < l1) { double tl = l0; l0 = l1; l1 = tl; int ti = i0; i0 = i1; i1 = ti; }
    if (l0 < l2) { double tl = l0; l0 = l2; l2 = tl; int ti = i0; i0 = i2; i2 = ti; }
    if (l1 < l2) { double tl = l1; l1 = l2; l2 = tl; int ti = i1; i1 = i2; i2 = ti; }

    double s0 = sqrt(fmax(l0, 0.0)), s1 = sqrt(fmax(l1, 0.0)), s2 = sqrt(fmax(l2, 0.0));
    double detB = B[0][0] * (B[1][1] * B[2][2] - B[1][2] * B[2][1])
                - B[0][1] * (B[1][0] * B[2][2] - B[1][2] * B[2][0])
                + B[0][2] * (B[1][0] * B[2][1] - B[1][1] * B[2][0]);
    double d = (detB < 0.0) ? -1.0 : 1.0;
    double inv[3];
    inv[0] = 1.0 / fmax(s0, 1e-12);
    inv[1] = 1.0 / fmax(s1, 1e-12);
    inv[2] = d   / fmax(s2, 1e-12);

    double Vs[3][3];
#pragma unroll
    for (int r = 0; r < 3; r++) { Vs[r][0] = V[r][i0]; Vs[r][1] = V[r][i1]; Vs[r][2] = V[r][i2]; }

    double T[3][3];
#pragma unroll
    for (int r = 0; r < 3; r++)
#pragma unroll
        for (int j = 0; j < 3; j++)
            T[r][j] = (B[r][0] * Vs[0][j] + B[r][1] * Vs[1][j] + B[r][2] * Vs[2][j]) * inv[j];
    double R[3][3];
#pragma unroll
    for (int r = 0; r < 3; r++)
#pragma unroll
        for (int c = 0; c < 3; c++)
            R[r][c] = T[r][0] * Vs[c][0] + T[r][1] * Vs[c][1] + T[r][2] * Vs[c][2];

    float* o = out + (size_t)i * 16;
    o[0]  = (float)R[0][0]; o[1]  = (float)R[0][1]; o[2]  = (float)R[0][2]; o[3]  = tvec[i * 3 + 0];
    o[4]  = (float)R[1][0]; o[5]  = (float)R[1][1]; o[6]  = (float)R[1][2]; o[7]  = tvec[i * 3 + 1];
    o[8]  = (float)R[2][0]; o[9]  = (float)R[2][1]; o[10] = (float)R[2][2]; o[11] = tvec[i * 3 + 2];
    o[12] = 0.f; o[13] = 0.f; o[14] = 0.f; o[15] = 1.f;
}

// ---------------- launch ----------------
extern "C" void kernel_launch(void* const* d_in, const int* in_sizes, int n_in,
                              void* d_out, int out_size)
{
    const float* feat   = (const float*)d_in[0];
    const float* W_res  = (const float*)d_in[5];
    const float* b_res  = (const float*)d_in[6];
    const float* W_cur1 = (const float*)d_in[7];
    const float* b_cur1 = (const float*)d_in[8];
    const float* W_cur2 = (const float*)d_in[9];
    const float* b_cur2 = (const float*)d_in[10];
    const float* W_tp1  = (const float*)d_in[11];
    const float* b_tp1  = (const float*)d_in[12];
    const float* W_tp2  = (const float*)d_in[13];
    const float* b_tp2  = (const float*)d_in[14];
    const float* W_fut1 = (const float*)d_in[15];
    const float* b_fut1 = (const float*)d_in[16];
    const float* W_fut2 = (const float*)d_in[17];
    const float* b_fut2 = (const float*)d_in[18];
    const float* W_m1   = (const float*)d_in[19];
    const float* b_m1   = (const float*)d_in[20];
    const float* W_m2   = (const float*)d_in[21];
    const float* b_m2   = (const float*)d_in[22];
    const float* W_t    = (const float*)d_in[23];
    const float* b_t    = (const float*)d_in[24];
    const float* W_r    = (const float*)d_in[25];
    const float* b_r    = (const float*)d_in[26];

    __nv_bfloat16 *fH, *fL, *t1H, *t1L, *t2H, *t2L, *x3H, *x3L, *wH, *wL;
    float *pooled, *gctx, *s1, *s2, *tf, *allf, *s3, *s4, *tvec, *rmat;
    cudaGetSymbolAddress((void**)&fH,  g_fH);  cudaGetSymbolAddress((void**)&fL,  g_fL);
    cudaGetSymbolAddress((void**)&t1H, g_t1H); cudaGetSymbolAddress((void**)&t1L, g_t1L);
    cudaGetSymbolAddress((void**)&t2H, g_t2H); cudaGetSymbolAddress((void**)&t2L, g_t2L);
    cudaGetSymbolAddress((void**)&x3H, g_x3H); cudaGetSymbolAddress((void**)&x3L, g_x3L);
    cudaGetSymbolAddress((void**)&wH,  g_wH);  cudaGetSymbolAddress((void**)&wL,  g_wL);
    cudaGetSymbolAddress((void**)&pooled, g_pooled);
    cudaGetSymbolAddress((void**)&gctx,   g_gctx);
    cudaGetSymbolAddress((void**)&s1,     g_s1);
    cudaGetSymbolAddress((void**)&s2,     g_s2);
    cudaGetSymbolAddress((void**)&tf,     g_tf);
    cudaGetSymbolAddress((void**)&allf,   g_allf);
    cudaGetSymbolAddress((void**)&s3,     g_s3);
    cudaGetSymbolAddress((void**)&s4,     g_s4);
    cudaGetSymbolAddress((void**)&tvec,   g_t);
    cudaGetSymbolAddress((void**)&rmat,   g_r);

    cudaFuncSetAttribute(gemm_mma, cudaFuncAttributeMaxDynamicSharedMemorySize, SMEM_TOTAL);

    // weight split + feat split
    wprep_kernel<<<6 * D * D / 256, 256>>>(W_res, wH, wL);
    split_kernel<<<4096, 256>>>((const float4*)feat, (__nv_bfloat162*)fH, (__nv_bfloat162*)fL,
                                (size_t)MROWS * D / 4);

    const size_t WS = (size_t)D * D;
    dim3 gg(4, (MROWS + 127) / 128);

    // ResConvBlock 0
    gemm_mma<<<gg, 256, SMEM_TOTAL>>>(fH, fL, wH + 0 * WS, wL + 0 * WS, b_res + 0 * D,
                                      nullptr, nullptr, nullptr, t1H, t1L, MROWS);
    gemm_mma<<<gg, 256, SMEM_TOTAL>>>(t1H, t1L, wH + 1 * WS, wL + 1 * WS, b_res + 1 * D,
                                      nullptr, nullptr, nullptr, t2H, t2L, MROWS);
    gemm_mma<<<gg, 256, SMEM_TOTAL>>>(t2H, t2L, wH + 2 * WS, wL + 2 * WS, b_res + 2 * D,
                                      feat, nullptr, nullptr, x3H, x3L, MROWS);
    // ResConvBlock 1
    gemm_mma<<<gg, 256, SMEM_TOTAL>>>(x3H, x3L, wH + 3 * WS, wL + 3 * WS, b_res + 3 * D,
                                      nullptr, nullptr, nullptr, t1H, t1L, MROWS);
    gemm_mma<<<gg, 256, SMEM_TOTAL>>>(t1H, t1L, wH + 4 * WS, wL + 4 * WS, b_res + 4 * D,
                                      nullptr, nullptr, nullptr, t2H, t2L, MROWS);
    gemm_mma<<<gg, 256, SMEM_TOTAL>>>(t2H, t2L, wH + 5 * WS, wL + 5 * WS, b_res + 5 * D,
                                      nullptr, x3H, x3L, fH, fL, MROWS);

    // pooled mean over hw (parallel + atomic)
    pool_zero<<<96, 512>>>(pooled);
    pool_atomic<<<dim3(96, 8), 512>>>(fH, fL, pooled);

    // current-frame MLP -> allf[0:96]
    small_gemm<<<dim3(4, 96), 128>>>(pooled, W_cur1, b_cur1, s1, 512, 1);
    small_gemm<<<dim3(4, 96), 128>>>(s1, W_cur2, b_cur2, allf, 512, 0);

    // global context -> temporal proj -> future MLP -> allf[96:192]
    gctx_kernel<<<32, 512>>>(pooled, gctx);
    small_gemm<<<dim3(4, 32), 128>>>(gctx, W_tp1, b_tp1, s2, 512, 1);
    small_gemm<<<dim3(12, 32), 128>>>(s2, W_tp2, b_tp2, tf, 1536, 0);
    small_gemm<<<dim3(4, 96), 128>>>(tf, W_fut1, b_fut1, s1, 512, 1);
    small_gemm<<<dim3(4, 96), 128>>>(s1, W_fut2, b_fut2, allf + 96 * D, 512, 0);

    // more_mlps
    small_gemm<<<dim3(4, 192), 128>>>(allf, W_m1, b_m1, s3, 512, 1);
    small_gemm<<<dim3(4, 192), 128>>>(s3, W_m2, b_m2, s4, 512, 1);

    // pose heads
    small_gemm<<<dim3(1, 192), 32>>>(s4, W_t, b_t, tvec, 3, 0);
    small_gemm<<<dim3(1, 192), 32>>>(s4, W_r, b_r, rmat, 9, 0);

    // SVD orthogonalize + assemble pose
    pose_svd_kernel<<<1, 192>>>(tvec, rmat, (float*)d_out);
}

// round 11
// speedup vs baseline: 1.1647x; 1.1647x over previous
#include <cuda_runtime.h>
#include <cuda_bf16.h>
#include <math.h>
#include <stdint.h>

#define D 512
#define MROWS (96*1369)   // 131424
#define NEWBN 192

// ---------------- scratch (device globals: allocation-free rule) ----------------
__device__ __nv_bfloat16 g_fH[(size_t)MROWS * D], g_fL[(size_t)MROWS * D];
__device__ __nv_bfloat16 g_t1H[(size_t)MROWS * D], g_t1L[(size_t)MROWS * D];
__device__ __nv_bfloat16 g_t2H[(size_t)MROWS * D], g_t2L[(size_t)MROWS * D];
__device__ __nv_bfloat16 g_x3H[(size_t)MROWS * D], g_x3L[(size_t)MROWS * D];
__device__ __nv_bfloat16 g_wH[6 * D * D], g_wL[6 * D * D];   // same layout as W: [l][k][n]
__device__ float g_pooled[96 * D];
__device__ float g_gctx[32 * D];
__device__ float g_s1[96 * D];
__device__ float g_s2[32 * D];
__device__ float g_tf[96 * D];
__device__ float g_allf[NEWBN * D];
__device__ float g_s3[NEWBN * D];
__device__ float g_s4[NEWBN * D];
__device__ float g_t[NEWBN * 3];
__device__ float g_r[NEWBN * 9];

// ---------------- PTX helpers (baseline ISA only: sm_80/75 features) ----------------
__device__ __forceinline__ uint32_t smem_u32(const void* p) {
    uint32_t a;
    asm("{ .reg .u64 t; cvta.to.shared.u64 t, %1; cvt.u32.u64 %0, t; }" : "=r"(a) : "l"(p));
    return a;
}

#define CPA16(dst, src, sz) asm volatile("cp.async.cg.shared.global [%0], [%1], 16, %2;" :: "r"(dst), "l"(src), "r"(sz) : "memory")
#define CP_COMMIT() asm volatile("cp.async.commit_group;" ::: "memory")
#define CP_WAIT1()  asm volatile("cp.async.wait_group 1;" ::: "memory")
#define CP_WAIT0()  asm volatile("cp.async.wait_group 0;" ::: "memory")

__device__ __forceinline__ void ldsm_x4(uint32_t& r0, uint32_t& r1, uint32_t& r2, uint32_t& r3, uint32_t a) {
    asm volatile("ldmatrix.sync.aligned.m8n8.x4.shared.b16 {%0,%1,%2,%3}, [%4];"
                 : "=r"(r0), "=r"(r1), "=r"(r2), "=r"(r3) : "r"(a));
}
__device__ __forceinline__ void ldsm_x4t(uint32_t& r0, uint32_t& r1, uint32_t& r2, uint32_t& r3, uint32_t a) {
    asm volatile("ldmatrix.sync.aligned.m8n8.x4.trans.shared.b16 {%0,%1,%2,%3}, [%4];"
                 : "=r"(r0), "=r"(r1), "=r"(r2), "=r"(r3) : "r"(a));
}
__device__ __forceinline__ void mma_bf16(float* c, const uint32_t* a, const uint32_t* b) {
    asm volatile("mma.sync.aligned.m16n8k16.row.col.f32.bf16.bf16.f32 "
                 "{%0,%1,%2,%3}, {%4,%5,%6,%7}, {%8,%9}, {%0,%1,%2,%3};"
                 : "+f"(c[0]), "+f"(c[1]), "+f"(c[2]), "+f"(c[3])
                 : "r"(a[0]), "r"(a[1]), "r"(a[2]), "r"(a[3]), "r"(b[0]), "r"(b[1]));
}

// ---------------- smem layout: BK=64 stages, 3-slot ring ----------------
#define ASTRIDE 72          // bf16 elems per A row (64 + 8 pad)
#define BSTRIDE 136         // bf16 elems per B k-row (128 + 8 pad)
#define A_BYTES (128 * ASTRIDE * 2)   // 18432
#define B_BYTES (64 * BSTRIDE * 2)    // 17408
#define STAGE_B (A_BYTES + B_BYTES)   // 35840
#define NBUF 3
#define SMEM_TOTAL (NBUF * STAGE_B)   // 107520 -> 2 CTAs/SM
#define NST 24             // 3 passes x 8 stages (BK=64, K=512)

// ---------------- mma.sync GEMM: out = [res +] relu(A @ W + bias), hi/lo split ----------------
// Effective: (AH+AL) @ (WH+WL) ~= AH@WH + AL@WH + AH@WL, K=3*512 loop, fp32 accum.
__global__ __launch_bounds__(256)
void gemm_mma(const __nv_bfloat16* __restrict__ AH, const __nv_bfloat16* __restrict__ AL,
              const __nv_bfloat16* __restrict__ BH, const __nv_bfloat16* __restrict__ BL,
              const float* __restrict__ bias,
              const float* __restrict__ resF,
              const __nv_bfloat16* __restrict__ resH, const __nv_bfloat16* __restrict__ resL,
              __nv_bfloat16* __restrict__ outH, __nv_bfloat16* __restrict__ outL,
              int M)
{
    extern __shared__ char smem[];
    const uint32_t sb = smem_u32(smem);
    const int tid = threadIdx.x;
    const int wid = tid >> 5, lane = tid & 31;
    const int bm = blockIdx.y * 128;
    const int nb = blockIdx.x * 128;
    const int wm = (wid & 1) * 64;    // warp row base in tile
    const int wn = (wid >> 1) * 32;   // warp col base in tile

    float acc[4][4][4];
#pragma unroll
    for (int i = 0; i < 4; i++)
#pragma unroll
        for (int j = 0; j < 4; j++)
#pragma unroll
            for (int k = 0; k < 4; k++) acc[i][j][k] = 0.f;

    // stage loader: 8 x 16B cp.async per thread (A: 1024 chunks, B: 1024 chunks)
    auto load_stage = [&](int gs, int buf) {
        const int p = gs >> 3;             // pass 0: AH*BH, 1: AL*BH, 2: AH*BL
        const int kc = (gs & 7) * 64;
        const __nv_bfloat16* Asrc = (p == 1) ? AL : AH;
        const __nv_bfloat16* Bsrc = (p == 2) ? BL : BH;
        const uint32_t base = sb + buf * STAGE_B;
        // A: 128 rows x 64k = 1024 x 16B chunks
#pragma unroll
        for (int i = 0; i < 4; i++) {
            int c = tid + 256 * i;
            int m = c >> 3, kk = c & 7;
            int row = bm + m;
            int sz = (row < M) ? 16 : 0;
            int rc = (row < M) ? row : 0;
            const __nv_bfloat16* s = Asrc + (size_t)rc * D + kc + kk * 8;
            CPA16(base + (uint32_t)(m * ASTRIDE + kk * 8) * 2, s, sz);
        }
        // B: 64 k-rows x 128n = 1024 x 16B chunks
#pragma unroll
        for (int i = 0; i < 4; i++) {
            int c = tid + 256 * i;
            int k = c >> 4, nn = c & 15;
            const __nv_bfloat16* s = Bsrc + (size_t)(kc + k) * D + nb + nn * 8;
            CPA16(base + A_BYTES + (uint32_t)(k * BSTRIDE + nn * 8) * 2, s, 16);
        }
    };

    load_stage(0, 0); CP_COMMIT();
    load_stage(1, 1); CP_COMMIT();

    const int lrow = lane & 15;        // ldmatrix row within 16
    const int lcol = (lane >> 4) * 8;  // ldmatrix col-half

    int cslot = 0;                     // s % 3
    int nslot = 2;                     // (s+2) % 3
    for (int s = 0; s < NST; s++) {
        if (s < NST - 1) { CP_WAIT1(); } else { CP_WAIT0(); }
        __syncthreads();
        // Safe: slot (s+2)%3 == slot (s-1)%3; all stage s-1 reads completed
        // before the barrier above, so the overwrite cannot race.
        if (s + 2 < NST) {
            load_stage(s + 2, nslot);
            CP_COMMIT();
        }

        const uint32_t aBase = sb + cslot * STAGE_B;
        const uint32_t bBase = aBase + A_BYTES;
#pragma unroll
        for (int ks = 0; ks < 64; ks += 16) {
            uint32_t a[4][4], b[4][2];
#pragma unroll
            for (int mf = 0; mf < 4; mf++) {
                uint32_t addr = aBase + (uint32_t)((wm + mf * 16 + lrow) * ASTRIDE + ks + lcol) * 2;
                ldsm_x4(a[mf][0], a[mf][1], a[mf][2], a[mf][3], addr);
            }
#pragma unroll
            for (int ng = 0; ng < 2; ng++) {
                uint32_t addr = bBase + (uint32_t)((ks + lrow) * BSTRIDE + wn + ng * 16 + lcol) * 2;
                ldsm_x4t(b[ng * 2][0], b[ng * 2][1], b[ng * 2 + 1][0], b[ng * 2 + 1][1], addr);
            }
#pragma unroll
            for (int mf = 0; mf < 4; mf++)
#pragma unroll
                for (int nf = 0; nf < 4; nf++)
                    mma_bf16(acc[mf][nf], a[mf], b[nf]);
        }
        cslot = (cslot == 2) ? 0 : cslot + 1;
        nslot = (nslot == 2) ? 0 : nslot + 1;
    }

    // ---- epilogue: bias + relu + residual, split-write bf16 hi/lo ----
    const int qr = lane >> 2;          // row within 8
    const int qc = (lane & 3) * 2;     // col pair
#pragma unroll
    for (int mf = 0; mf < 4; mf++) {
#pragma unroll
        for (int half = 0; half < 2; half++) {
            int row = bm + wm + mf * 16 + qr + half * 8;
            if (row >= M) continue;
#pragma unroll
            for (int nf = 0; nf < 4; nf++) {
                int col = nb + wn + nf * 8 + qc;
                float v0 = acc[mf][nf][half * 2 + 0] + bias[col];
                float v1 = acc[mf][nf][half * 2 + 1] + bias[col + 1];
                v0 = fmaxf(v0, 0.f);
                v1 = fmaxf(v1, 0.f);
                size_t base = (size_t)row * D + col;
                if (resF) {
                    v0 += resF[base];
                    v1 += resF[base + 1];
                } else if (resH) {
                    v0 += __bfloat162float(resH[base]) + __bfloat162float(resL[base]);
                    v1 += __bfloat162float(resH[base + 1]) + __bfloat162float(resL[base + 1]);
                }
                __nv_bfloat16 h0 = __float2bfloat16(v0);
                __nv_bfloat16 h1 = __float2bfloat16(v1);
                __nv_bfloat16 l0 = __float2bfloat16(v0 - __bfloat162float(h0));
                __nv_bfloat16 l1 = __float2bfloat16(v1 - __bfloat162float(h1));
                *reinterpret_cast<__nv_bfloat162*>(outH + base) = __halves2bfloat162(h0, h1);
                *reinterpret_cast<__nv_bfloat162*>(outL + base) = __halves2bfloat162(l0, l1);
            }
        }
    }
}

// ---------------- fp32 -> bf16 hi/lo split ----------------
__global__ void split_kernel(const float4* __restrict__ x,
                             __nv_bfloat162* __restrict__ h, __nv_bfloat162* __restrict__ l,
                             size_t n4)
{
    size_t i = (size_t)blockIdx.x * blockDim.x + threadIdx.x;
    size_t stride = (size_t)gridDim.x * blockDim.x;
    for (; i < n4; i += stride) {
        float4 v = x[i];
        __nv_bfloat16 h0 = __float2bfloat16(v.x), h1 = __float2bfloat16(v.y);
        __nv_bfloat16 h2 = __float2bfloat16(v.z), h3 = __float2bfloat16(v.w);
        h[2 * i]     = __halves2bfloat162(h0, h1);
        h[2 * i + 1] = __halves2bfloat162(h2, h3);
        l[2 * i]     = __halves2bfloat162(__float2bfloat16(v.x - __bfloat162float(h0)),
                                          __float2bfloat16(v.y - __bfloat162float(h1)));
        l[2 * i + 1] = __halves2bfloat162(__float2bfloat16(v.z - __bfloat162float(h2)),
                                          __float2bfloat16(v.w - __bfloat162float(h3)));
    }
}

// ---------------- weight split (same [l][k][n] layout) ----------------
__global__ void wprep_kernel(const float* __restrict__ W,
                             __nv_bfloat16* __restrict__ WH, __nv_bfloat16* __restrict__ WL)
{
    int idx = blockIdx.x * blockDim.x + threadIdx.x;   // < 6*512*512
    float v = W[idx];
    __nv_bfloat16 h = __float2bfloat16(v);
    WH[idx] = h;
    WL[idx] = __float2bfloat16(v - __bfloat162float(h));
}

// ---------------- mean over hw (1369): parallel partial sums + atomics ----------------
__global__ void pool_zero(float* __restrict__ pooled)
{
    pooled[blockIdx.x * blockDim.x + threadIdx.x] = 0.f;
}

__global__ void pool_atomic(const __nv_bfloat16* __restrict__ xh,
                            const __nv_bfloat16* __restrict__ xl, float* __restrict__ out)
{
    int bn = blockIdx.x;
    int chunk = blockIdx.y;
    int d = threadIdx.x;
    int r0 = chunk * 172;
    int r1 = r0 + 172; if (r1 > 1369) r1 = 1369;
    const __nv_bfloat16* ph = xh + (size_t)bn * 1369 * D + (size_t)r0 * D + d;
    const __nv_bfloat16* pl = xl + (size_t)bn * 1369 * D + (size_t)r0 * D + d;
    float s = 0.f;
    for (int i = 0; i < r1 - r0; i++)
        s += __bfloat162float(ph[(size_t)i * D]) + __bfloat162float(pl[(size_t)i * D]);
    atomicAdd(&out[bn * D + d], s * (1.0f / 1369.0f));
}

// ---------------- mean over N=3 frames ----------------
__global__ void gctx_kernel(const float* __restrict__ pooled, float* __restrict__ out)
{
    int b = blockIdx.x;
    int d = threadIdx.x;
    float s = pooled[(b * 3 + 0) * D + d] + pooled[(b * 3 + 1) * D + d] + pooled[(b * 3 + 2) * D + d];
    out[b * D + d] = s * (1.0f / 3.0f);
}

// ---------------- small GEMM: C[m,n] = act(A[m,:] @ W[:,n] + bias[n]), K=512 ----------------
__global__ void small_gemm(const float* __restrict__ A, const float* __restrict__ W,
                           const float* __restrict__ bias, float* __restrict__ C,
                           int N, int doRelu)
{
    int n = blockIdx.x * blockDim.x + threadIdx.x;
    int m = blockIdx.y;
    if (n >= N) return;
    const float* a = A + (size_t)m * D;
    const float* w = W + n;
    float s0 = 0.f, s1 = 0.f, s2 = 0.f, s3 = 0.f;
#pragma unroll 4
    for (int k = 0; k < D; k += 4) {
        s0 = fmaf(a[k + 0], w[(size_t)(k + 0) * N], s0);
        s1 = fmaf(a[k + 1], w[(size_t)(k + 1) * N], s1);
        s2 = fmaf(a[k + 2], w[(size_t)(k + 2) * N], s2);
        s3 = fmaf(a[k + 3], w[(size_t)(k + 3) * N], s3);
    }
    float s = ((s0 + s1) + (s2 + s3)) + bias[n];
    if (doRelu) s = fmaxf(s, 0.f);
    C[(size_t)m * N + n] = s;
}

// ---------------- special Procrustes SVD (3x3) + pose assembly ----------------
__device__ __forceinline__ void jrot(double H[3][3], double V[3][3], int p, int q)
{
    double apq = H[p][q];
    if (fabs(apq) < 1e-300) return;
    double theta = (H[q][q] - H[p][p]) / (2.0 * apq);
    double t = ((theta >= 0.0) ? 1.0 : -1.0) / (fabs(theta) + sqrt(theta * theta + 1.0));
    double c = 1.0 / sqrt(t * t + 1.0);
    double sn = t * c;
#pragma unroll
    for (int k = 0; k < 3; k++) {
        double hkp = H[k][p], hkq = H[k][q];
        H[k][p] = c * hkp - sn * hkq;
        H[k][q] = sn * hkp + c * hkq;
    }
#pragma unroll
    for (int k = 0; k < 3; k++) {
        double hpk = H[p][k], hqk = H[q][k];
        H[p][k] = c * hpk - sn * hqk;
        H[q][k] = sn * hpk + c * hqk;
    }
#pragma unroll
    for (int k = 0; k < 3; k++) {
        double vkp = V[k][p], vkq = V[k][q];
        V[k][p] = c * vkp - sn * vkq;
        V[k][q] = sn * vkp + c * vkq;
    }
}

__global__ void pose_svd_kernel(const float* __restrict__ tvec,
                                const float* __restrict__ rmat,
                                float* __restrict__ out)
{
    int i = blockIdx.x * blockDim.x + threadIdx.x;
    if (i >= NEWBN) return;

    double B[3][3];
#pragma unroll
    for (int r = 0; r < 3; r++) {
        double a0 = (double)rmat[i * 9 + r * 3 + 0];
        double a1 = (double)rmat[i * 9 + r * 3 + 1];
        double a2 = (double)rmat[i * 9 + r * 3 + 2];
        double nrm = sqrt(a0 * a0 + a1 * a1 + a2 * a2);
        nrm = fmax(nrm, 1e-12);
        B[r][0] = a0 / nrm; B[r][1] = a1 / nrm; B[r][2] = a2 / nrm;
    }
    double H[3][3];
#pragma unroll
    for (int r = 0; r < 3; r++)
#pragma unroll
        for (int c = 0; c < 3; c++)
            H[r][c] = B[0][r] * B[0][c] + B[1][r] * B[1][c] + B[2][r] * B[2][c];

    double V[3][3] = {{1,0,0},{0,1,0},{0,0,1}};
    for (int sweep = 0; sweep < 15; sweep++) {
        jrot(H, V, 0, 1);
        jrot(H, V, 0, 2);
        jrot(H, V, 1, 2);
    }
    double l0 = H[0][0], l1 = H[1][1], l2 = H[2][2];
    int i0 = 0, i1 = 1, i2 = 2;
    if (l0 < l1) { double tl = l0; l0 = l1; l1 = tl; int ti = i0; i0 = i1; i1 = ti; }
    if (l0 < l2) { double tl = l0; l0 = l2; l2 = tl; int ti = i0; i0 = i2; i2 = ti; }
    if (l1 < l2) { double tl = l1; l1 = l2; l2 = tl; int ti = i1; i1 = i2; i2 = ti; }

    double s0 = sqrt(fmax(l0, 0.0)), s1 = sqrt(fmax(l1, 0.0)), s2 = sqrt(fmax(l2, 0.0));
    double detB = B[0][0] * (B[1][1] * B[2][2] - B[1][2] * B[2][1])
                - B[0][1] * (B[1][0] * B[2][2] - B[1][2] * B[2][0])
                + B[0][2] * (B[1][0] * B[2][1] - B[1][1] * B[2][0]);
    double d = (detB < 0.0) ? -1.0 : 1.0;
    double inv[3];
    inv[0] = 1.0 / fmax(s0, 1e-12);
    inv[1] = 1.0 / fmax(s1, 1e-12);
    inv[2] = d   / fmax(s2, 1e-12);

    double Vs[3][3];
#pragma unroll
    for (int r = 0; r < 3; r++) { Vs[r][0] = V[r][i0]; Vs[r][1] = V[r][i1]; Vs[r][2] = V[r][i2]; }

    double T[3][3];
#pragma unroll
    for (int r = 0; r < 3; r++)
#pragma unroll
        for (int j = 0; j < 3; j++)
            T[r][j] = (B[r][0] * Vs[0][j] + B[r][1] * Vs[1][j] + B[r][2] * Vs[2][j]) * inv[j];
    double R[3][3];
#pragma unroll
    for (int r = 0; r < 3; r++)
#pragma unroll
        for (int c = 0; c < 3; c++)
            R[r][c] = T[r][0] * Vs[c][0] + T[r][1] * Vs[c][1] + T[r][2] * Vs[c][2];

    float* o = out + (size_t)i * 16;
    o[0]  = (float)R[0][0]; o[1]  = (float)R[0][1]; o[2]  = (float)R[0][2]; o[3]  = tvec[i * 3 + 0];
    o[4]  = (float)R[1][0]; o[5]  = (float)R[1][1]; o[6]  = (float)R[1][2]; o[7]  = tvec[i * 3 + 1];
    o[8]  = (float)R[2][0]; o[9]  = (float)R[2][1]; o[10] = (float)R[2][2]; o[11] = tvec[i * 3 + 2];
    o[12] = 0.f; o[13] = 0.f; o[14] = 0.f; o[15] = 1.f;
}

// ---------------- launch ----------------
extern "C" void kernel_launch(void* const* d_in, const int* in_sizes, int n_in,
                              void* d_out, int out_size)
{
    const float* feat   = (const float*)d_in[0];
    const float* W_res  = (const float*)d_in[5];
    const float* b_res  = (const float*)d_in[6];
    const float* W_cur1 = (const float*)d_in[7];
    const float* b_cur1 = (const float*)d_in[8];
    const float* W_cur2 = (const float*)d_in[9];
    const float* b_cur2 = (const float*)d_in[10];
    const float* W_tp1  = (const float*)d_in[11];
    const float* b_tp1  = (const float*)d_in[12];
    const float* W_tp2  = (const float*)d_in[13];
    const float* b_tp2  = (const float*)d_in[14];
    const float* W_fut1 = (const float*)d_in[15];
    const float* b_fut1 = (const float*)d_in[16];
    const float* W_fut2 = (const float*)d_in[17];
    const float* b_fut2 = (const float*)d_in[18];
    const float* W_m1   = (const float*)d_in[19];
    const float* b_m1   = (const float*)d_in[20];
    const float* W_m2   = (const float*)d_in[21];
    const float* b_m2   = (const float*)d_in[22];
    const float* W_t    = (const float*)d_in[23];
    const float* b_t    = (const float*)d_in[24];
    const float* W_r    = (const float*)d_in[25];
    const float* b_r    = (const float*)d_in[26];

    __nv_bfloat16 *fH, *fL, *t1H, *t1L, *t2H, *t2L, *x3H, *x3L, *wH, *wL;
    float *pooled, *gctx, *s1, *s2, *tf, *allf, *s3, *s4, *tvec, *rmat;
    cudaGetSymbolAddress((void**)&fH,  g_fH);  cudaGetSymbolAddress((void**)&fL,  g_fL);
    cudaGetSymbolAddress((void**)&t1H, g_t1H); cudaGetSymbolAddress((void**)&t1L, g_t1L);
    cudaGetSymbolAddress((void**)&t2H, g_t2H); cudaGetSymbolAddress((void**)&t2L, g_t2L);
    cudaGetSymbolAddress((void**)&x3H, g_x3H); cudaGetSymbolAddress((void**)&x3L, g_x3L);
    cudaGetSymbolAddress((void**)&wH,  g_wH);  cudaGetSymbolAddress((void**)&wL,  g_wL);
    cudaGetSymbolAddress((void**)&pooled, g_pooled);
    cudaGetSymbolAddress((void**)&gctx,   g_gctx);
    cudaGetSymbolAddress((void**)&s1,     g_s1);
    cudaGetSymbolAddress((void**)&s2,     g_s2);
    cudaGetSymbolAddress((void**)&tf,     g_tf);
    cudaGetSymbolAddress((void**)&allf,   g_allf);
    cudaGetSymbolAddress((void**)&s3,     g_s3);
    cudaGetSymbolAddress((void**)&s4,     g_s4);
    cudaGetSymbolAddress((void**)&tvec,   g_t);
    cudaGetSymbolAddress((void**)&rmat,   g_r);

    cudaFuncSetAttribute(gemm_mma, cudaFuncAttributeMaxDynamicSharedMemorySize, SMEM_TOTAL);

    // weight split + feat split
    wprep_kernel<<<6 * D * D / 256, 256>>>(W_res, wH, wL);
    split_kernel<<<4096, 256>>>((const float4*)feat, (__nv_bfloat162*)fH, (__nv_bfloat162*)fL,
                                (size_t)MROWS * D / 4);

    const size_t WS = (size_t)D * D;
    dim3 gg(4, (MROWS + 127) / 128);

    // ResConvBlock 0
    gemm_mma<<<gg, 256, SMEM_TOTAL>>>(fH, fL, wH + 0 * WS, wL + 0 * WS, b_res + 0 * D,
                                      nullptr, nullptr, nullptr, t1H, t1L, MROWS);
    gemm_mma<<<gg, 256, SMEM_TOTAL>>>(t1H, t1L, wH + 1 * WS, wL + 1 * WS, b_res + 1 * D,
                                      nullptr, nullptr, nullptr, t2H, t2L, MROWS);
    gemm_mma<<<gg, 256, SMEM_TOTAL>>>(t2H, t2L, wH + 2 * WS, wL + 2 * WS, b_res + 2 * D,
                                      feat, nullptr, nullptr, x3H, x3L, MROWS);
    // ResConvBlock 1
    gemm_mma<<<gg, 256, SMEM_TOTAL>>>(x3H, x3L, wH + 3 * WS, wL + 3 * WS, b_res + 3 * D,
                                      nullptr, nullptr, nullptr, t1H, t1L, MROWS);
    gemm_mma<<<gg, 256, SMEM_TOTAL>>>(t1H, t1L, wH + 4 * WS, wL + 4 * WS, b_res + 4 * D,
                                      nullptr, nullptr, nullptr, t2H, t2L, MROWS);
    gemm_mma<<<gg, 256, SMEM_TOTAL>>>(t2H, t2L, wH + 5 * WS, wL + 5 * WS, b_res + 5 * D,
                                      nullptr, x3H, x3L, fH, fL, MROWS);

    // pooled mean over hw (parallel + atomic)
    pool_zero<<<96, 512>>>(pooled);
    pool_atomic<<<dim3(96, 8), 512>>>(fH, fL, pooled);

    // current-frame MLP -> allf[0:96]
    small_gemm<<<dim3(4, 96), 128>>>(pooled, W_cur1, b_cur1, s1, 512, 1);
    small_gemm<<<dim3(4, 96), 128>>>(s1, W_cur2, b_cur2, allf, 512, 0);

    // global context -> temporal proj -> future MLP -> allf[96:192]
    gctx_kernel<<<32, 512>>>(pooled, gctx);
    small_gemm<<<dim3(4, 32), 128>>>(gctx, W_tp1, b_tp1, s2, 512, 1);
    small_gemm<<<dim3(12, 32), 128>>>(s2, W_tp2, b_tp2, tf, 1536, 0);
    small_gemm<<<dim3(4, 96), 128>>>(tf, W_fut1, b_fut1, s1, 512, 1);
    small_gemm<<<dim3(4, 96), 128>>>(s1, W_fut2, b_fut2, allf + 96 * D, 512, 0);

    // more_mlps
    small_gemm<<<dim3(4, 192), 128>>>(allf, W_m1, b_m1, s3, 512, 1);
    small_gemm<<<dim3(4, 192), 128>>>(s3, W_m2, b_m2, s4, 512, 1);

    // pose heads
    small_gemm<<<dim3(1, 192), 32>>>(s4, W_t, b_t, tvec, 3, 0);
    small_gemm<<<dim3(1, 192), 32>>>(s4, W_r, b_r, rmat, 9, 0);

    // SVD orthogonalize + assemble pose
    pose_svd_kernel<<<1, 192>>>(tvec, rmat, (float*)d_out);
}

// round 13
// speedup vs baseline: 1.2871x; 1.1051x over previous
#include <cuda_runtime.h>
#include <cuda_bf16.h>
#include <math.h>
#include <stdint.h>

#define D 512
#define MROWS (96*1369)   // 131424
#define NEWBN 192

// ---------------- scratch (device globals: allocation-free rule) ----------------
__device__ __nv_bfloat16 g_fH[(size_t)MROWS * D], g_fL[(size_t)MROWS * D];
__device__ __nv_bfloat16 g_t1H[(size_t)MROWS * D], g_t1L[(size_t)MROWS * D];
__device__ __nv_bfloat16 g_t2H[(size_t)MROWS * D], g_t2L[(size_t)MROWS * D];
__device__ __nv_bfloat16 g_x3H[(size_t)MROWS * D], g_x3L[(size_t)MROWS * D];
__device__ float g_poolsrc[(size_t)MROWS * D];               // fp32 output of last GEMM
__device__ __nv_bfloat16 g_wH[6 * D * D], g_wL[6 * D * D];   // same layout as W: [l][k][n]
__device__ float g_pooled[96 * D];
__device__ float g_allf[NEWBN * D];
__device__ float g_tf[96 * D];

// ---------------- PTX helpers (baseline ISA only: sm_80/75 features) ----------------
__device__ __forceinline__ uint32_t smem_u32(const void* p) {
    uint32_t a;
    asm("{ .reg .u64 t; cvta.to.shared.u64 t, %1; cvt.u32.u64 %0, t; }" : "=r"(a) : "l"(p));
    return a;
}

#define CPA16(dst, src, sz) asm volatile("cp.async.cg.shared.global [%0], [%1], 16, %2;" :: "r"(dst), "l"(src), "r"(sz) : "memory")
#define CP_COMMIT() asm volatile("cp.async.commit_group;" ::: "memory")
#define CP_WAIT2()  asm volatile("cp.async.wait_group 2;" ::: "memory")

__device__ __forceinline__ void ldsm_x4(uint32_t& r0, uint32_t& r1, uint32_t& r2, uint32_t& r3, uint32_t a) {
    asm volatile("ldmatrix.sync.aligned.m8n8.x4.shared.b16 {%0,%1,%2,%3}, [%4];"
                 : "=r"(r0), "=r"(r1), "=r"(r2), "=r"(r3) : "r"(a));
}
__device__ __forceinline__ void ldsm_x4t(uint32_t& r0, uint32_t& r1, uint32_t& r2, uint32_t& r3, uint32_t a) {
    asm volatile("ldmatrix.sync.aligned.m8n8.x4.trans.shared.b16 {%0,%1,%2,%3}, [%4];"
                 : "=r"(r0), "=r"(r1), "=r"(r2), "=r"(r3) : "r"(a));
}
__device__ __forceinline__ void mma_bf16(float* c, const uint32_t* a, const uint32_t* b) {
    asm volatile("mma.sync.aligned.m16n8k16.row.col.f32.bf16.bf16.f32 "
                 "{%0,%1,%2,%3}, {%4,%5,%6,%7}, {%8,%9}, {%0,%1,%2,%3};"
                 : "+f"(c[0]), "+f"(c[1]), "+f"(c[2]), "+f"(c[3])
                 : "r"(a[0]), "r"(a[1]), "r"(a[2]), "r"(a[3]), "r"(b[0]), "r"(b[1]));
}

// ---------------- smem layout: BK=32, 4-slot ring (empirically best: R3 config) ----------------
#define ASTRIDE 40          // bf16 elems per A row (32 + 8 pad)
#define BSTRIDE 136         // bf16 elems per B k-row (128 + 8 pad)
#define A_BYTES (128 * ASTRIDE * 2)   // 10240
#define B_BYTES (32 * BSTRIDE * 2)    // 8704
#define STAGE_B (A_BYTES + B_BYTES)   // 18944
#define NBUF 4
#define SMEM_TOTAL (NBUF * STAGE_B)   // 75776 -> 2 CTAs/SM
#define NST 48             // 3 passes x 16 stages (BK=32, K=512)

// ---------------- mma.sync GEMM: out = [res +] relu(A @ W + bias), hi/lo split ----------------
// Effective: (AH+AL) @ (WH+WL) ~= AH@WH + AL@WH + AH@WL, K=3*512 loop, fp32 accum.
// If outF != nullptr, writes fp32 only (last layer feeding the pool).
__global__ __launch_bounds__(256)
void gemm_mma(const __nv_bfloat16* __restrict__ AH, const __nv_bfloat16* __restrict__ AL,
              const __nv_bfloat16* __restrict__ BH, const __nv_bfloat16* __restrict__ BL,
              const float* __restrict__ bias,
              const float* __restrict__ resF,
              const __nv_bfloat16* __restrict__ resH, const __nv_bfloat16* __restrict__ resL,
              __nv_bfloat16* __restrict__ outH, __nv_bfloat16* __restrict__ outL,
              float* __restrict__ outF,
              int M)
{
    extern __shared__ char smem[];
    const uint32_t sb = smem_u32(smem);
    const int tid = threadIdx.x;
    const int wid = tid >> 5, lane = tid & 31;
    const int bm = blockIdx.y * 128;
    const int nb = blockIdx.x * 128;
    const int wm = (wid & 1) * 64;    // warp row base in tile
    const int wn = (wid >> 1) * 32;   // warp col base in tile

    float acc[4][4][4];
#pragma unroll
    for (int i = 0; i < 4; i++)
#pragma unroll
        for (int j = 0; j < 4; j++)
#pragma unroll
            for (int k = 0; k < 4; k++) acc[i][j][k] = 0.f;

    // stage loader: 4 x 16B cp.async per thread
    auto load_stage = [&](int gs, int buf) {
        const int p = gs >> 4;             // pass 0: AH*BH, 1: AL*BH, 2: AH*BL
        const int kc = (gs & 15) * 32;
        const __nv_bfloat16* Asrc = (p == 1) ? AL : AH;
        const __nv_bfloat16* Bsrc = (p == 2) ? BL : BH;
        const uint32_t base = sb + buf * STAGE_B;
        // A: 128 rows x 32k = 512 x 16B chunks
#pragma unroll
        for (int i = 0; i < 2; i++) {
            int c = tid + 256 * i;
            int m = c >> 2, kk = c & 3;
            int row = bm + m;
            int sz = (row < M) ? 16 : 0;
            int rc = (row < M) ? row : 0;
            const __nv_bfloat16* s = Asrc + (size_t)rc * D + kc + kk * 8;
            CPA16(base + (uint32_t)(m * ASTRIDE + kk * 8) * 2, s, sz);
        }
        // B: 32 k-rows x 128n = 512 x 16B chunks
#pragma unroll
        for (int i = 0; i < 2; i++) {
            int c = tid + 256 * i;
            int k = c >> 4, nn = c & 15;
            const __nv_bfloat16* s = Bsrc + (size_t)(kc + k) * D + nb + nn * 8;
            CPA16(base + A_BYTES + (uint32_t)(k * BSTRIDE + nn * 8) * 2, s, 16);
        }
    };

    load_stage(0, 0); CP_COMMIT();
    load_stage(1, 1); CP_COMMIT();
    load_stage(2, 2); CP_COMMIT();

    const int lrow = lane & 15;        // ldmatrix row within 16
    const int lcol = (lane >> 4) * 8;  // ldmatrix col-half

    for (int s = 0; s < NST; s++) {
        CP_WAIT2();
        __syncthreads();
        if (s + 3 < NST) load_stage(s + 3, (s + 3) & 3);
        CP_COMMIT();

        const uint32_t aBase = sb + (s & 3) * STAGE_B;
        const uint32_t bBase = aBase + A_BYTES;
#pragma unroll
        for (int ks = 0; ks < 32; ks += 16) {
            uint32_t a[4][4], b[4][2];
#pragma unroll
            for (int mf = 0; mf < 4; mf++) {
                uint32_t addr = aBase + (uint32_t)((wm + mf * 16 + lrow) * ASTRIDE + ks + lcol) * 2;
                ldsm_x4(a[mf][0], a[mf][1], a[mf][2], a[mf][3], addr);
            }
#pragma unroll
            for (int ng = 0; ng < 2; ng++) {
                uint32_t addr = bBase + (uint32_t)((ks + lrow) * BSTRIDE + wn + ng * 16 + lcol) * 2;
                ldsm_x4t(b[ng * 2][0], b[ng * 2][1], b[ng * 2 + 1][0], b[ng * 2 + 1][1], addr);
            }
#pragma unroll
            for (int mf = 0; mf < 4; mf++)
#pragma unroll
                for (int nf = 0; nf < 4; nf++)
                    mma_bf16(acc[mf][nf], a[mf], b[nf]);
        }
        __syncthreads();
    }

    // ---- epilogue: bias + relu + residual ----
    const int qr = lane >> 2;          // row within 8
    const int qc = (lane & 3) * 2;     // col pair
#pragma unroll
    for (int mf = 0; mf < 4; mf++) {
#pragma unroll
        for (int half = 0; half < 2; half++) {
            int row = bm + wm + mf * 16 + qr + half * 8;
            if (row >= M) continue;
#pragma unroll
            for (int nf = 0; nf < 4; nf++) {
                int col = nb + wn + nf * 8 + qc;
                float v0 = acc[mf][nf][half * 2 + 0] + bias[col];
                float v1 = acc[mf][nf][half * 2 + 1] + bias[col + 1];
                v0 = fmaxf(v0, 0.f);
                v1 = fmaxf(v1, 0.f);
                size_t base = (size_t)row * D + col;
                if (resF) {
                    v0 += resF[base];
                    v1 += resF[base + 1];
                } else if (resH) {
                    v0 += __bfloat162float(resH[base]) + __bfloat162float(resL[base]);
                    v1 += __bfloat162float(resH[base + 1]) + __bfloat162float(resL[base + 1]);
                }
                if (outF) {
                    *reinterpret_cast<float2*>(outF + base) = make_float2(v0, v1);
                } else {
                    __nv_bfloat16 h0 = __float2bfloat16(v0);
                    __nv_bfloat16 h1 = __float2bfloat16(v1);
                    __nv_bfloat16 l0 = __float2bfloat16(v0 - __bfloat162float(h0));
                    __nv_bfloat16 l1 = __float2bfloat16(v1 - __bfloat162float(h1));
                    *reinterpret_cast<__nv_bfloat162*>(outH + base) = __halves2bfloat162(h0, h1);
                    *reinterpret_cast<__nv_bfloat162*>(outL + base) = __halves2bfloat162(l0, l1);
                }
            }
        }
    }
}

// ---------------- fp32 -> bf16 hi/lo split ----------------
__global__ void split_kernel(const float4* __restrict__ x,
                             __nv_bfloat162* __restrict__ h, __nv_bfloat162* __restrict__ l,
                             size_t n4)
{
    size_t i = (size_t)blockIdx.x * blockDim.x + threadIdx.x;
    size_t stride = (size_t)gridDim.x * blockDim.x;
    for (; i < n4; i += stride) {
        float4 v = x[i];
        __nv_bfloat16 h0 = __float2bfloat16(v.x), h1 = __float2bfloat16(v.y);
        __nv_bfloat16 h2 = __float2bfloat16(v.z), h3 = __float2bfloat16(v.w);
        h[2 * i]     = __halves2bfloat162(h0, h1);
        h[2 * i + 1] = __halves2bfloat162(h2, h3);
        l[2 * i]     = __halves2bfloat162(__float2bfloat16(v.x - __bfloat162float(h0)),
                                          __float2bfloat16(v.y - __bfloat162float(h1)));
        l[2 * i + 1] = __halves2bfloat162(__float2bfloat16(v.z - __bfloat162float(h2)),
                                          __float2bfloat16(v.w - __bfloat162float(h3)));
    }
}

// ---------------- weight split (same [l][k][n] layout) ----------------
__global__ void wprep_kernel(const float* __restrict__ W,
                             __nv_bfloat16* __restrict__ WH, __nv_bfloat16* __restrict__ WL)
{
    int idx = blockIdx.x * blockDim.x + threadIdx.x;   // < 6*512*512
    float v = W[idx];
    __nv_bfloat16 h = __float2bfloat16(v);
    WH[idx] = h;
    WL[idx] = __float2bfloat16(v - __bfloat162float(h));
}

// ---------------- mean over hw (1369): parallel partial sums + atomics, fp32 src ----------------
__global__ void pool_zero(float* __restrict__ pooled)
{
    pooled[blockIdx.x * blockDim.x + threadIdx.x] = 0.f;
}

__global__ void pool_atomic(const float* __restrict__ x, float* __restrict__ out)
{
    int bn = blockIdx.x;
    int chunk = blockIdx.y;
    int d = threadIdx.x;
    int r0 = chunk * 172;
    int r1 = r0 + 172; if (r1 > 1369) r1 = 1369;
    const float* p = x + (size_t)bn * 1369 * D + (size_t)r0 * D + d;
    float s = 0.f;
    for (int i = 0; i < r1 - r0; i++)
        s += p[(size_t)i * D];
    atomicAdd(&out[bn * D + d], s * (1.0f / 1369.0f));
}

// ---------------- fused two-layer MLP: OUT[m] = act2( relu(X[m]@W1+b1) @ W2 + b2 ) ----------------
__global__ __launch_bounds__(512)
void mlp2(const float* __restrict__ X,
          const float* __restrict__ W1, const float* __restrict__ b1,
          const float* __restrict__ W2, const float* __restrict__ b2,
          float* __restrict__ OUT, int N2, int relu2)
{
    __shared__ float xs[D];
    __shared__ float hs[D];
    int m = blockIdx.x, t = threadIdx.x;
    xs[t] = X[(size_t)m * D + t];
    __syncthreads();
    float s = b1[t];
#pragma unroll 8
    for (int k = 0; k < D; k++) s = fmaf(xs[k], W1[(size_t)k * D + t], s);
    hs[t] = fmaxf(s, 0.f);
    __syncthreads();
    for (int n = t; n < N2; n += D) {
        float s2 = b2[n];
#pragma unroll 8
        for (int k = 0; k < D; k++) s2 = fmaf(hs[k], W2[(size_t)k * N2 + n], s2);
        if (relu2) s2 = fmaxf(s2, 0.f);
        OUT[(size_t)m * N2 + n] = s2;
    }
}

// ---------------- temporal proj: gctx = mean3(pooled) -> 2-layer MLP -> tf [32][1536] ----------------
__global__ __launch_bounds__(512)
void tp_mlp(const float* __restrict__ pooled,
            const float* __restrict__ W1, const float* __restrict__ b1,
            const float* __restrict__ W2, const float* __restrict__ b2,
            float* __restrict__ tf)
{
    __shared__ float xs[D];
    __shared__ float hs[D];
    int b = blockIdx.x, t = threadIdx.x;
    xs[t] = (pooled[(b * 3 + 0) * D + t] + pooled[(b * 3 + 1) * D + t] +
             pooled[(b * 3 + 2) * D + t]) * (1.0f / 3.0f);
    __syncthreads();
    float s = b1[t];
#pragma unroll 8
    for (int k = 0; k < D; k++) s = fmaf(xs[k], W1[(size_t)k * D + t], s);
    hs[t] = fmaxf(s, 0.f);
    __syncthreads();
    const int N2 = 3 * D;
    for (int n = t; n < N2; n += D) {
        float s2 = b2[n];
#pragma unroll 8
        for (int k = 0; k < D; k++) s2 = fmaf(hs[k], W2[(size_t)k * N2 + n], s2);
        tf[(size_t)b * N2 + n] = s2;
    }
}

// ---------------- head: m1+m2 MLPs + pose heads + fp32 3x3 special-Procrustes SVD ----------------
__device__ __forceinline__ void jrotf(float H[3][3], float V[3][3], int p, int q)
{
    float apq = H[p][q];
    if (fabsf(apq) < 1e-30f) return;
    float theta = (H[q][q] - H[p][p]) / (2.0f * apq);
    float tt = ((theta >= 0.0f) ? 1.0f : -1.0f) / (fabsf(theta) + sqrtf(theta * theta + 1.0f));
    float c = rsqrtf(tt * tt + 1.0f);
    float sn = tt * c;
#pragma unroll
    for (int k = 0; k < 3; k++) {
        float hkp = H[k][p], hkq = H[k][q];
        H[k][p] = c * hkp - sn * hkq;
        H[k][q] = sn * hkp + c * hkq;
    }
#pragma unroll
    for (int k = 0; k < 3; k++) {
        float hpk = H[p][k], hqk = H[q][k];
        H[p][k] = c * hpk - sn * hqk;
        H[q][k] = sn * hpk + c * hqk;
    }
#pragma unroll
    for (int k = 0; k < 3; k++) {
        float vkp = V[k][p], vkq = V[k][q];
        V[k][p] = c * vkp - sn * vkq;
        V[k][q] = sn * vkp + c * vkq;
    }
}

__global__ __launch_bounds__(512)
void head_kernel(const float* __restrict__ allf,
                 const float* __restrict__ Wm1, const float* __restrict__ bm1,
                 const float* __restrict__ Wm2, const float* __restrict__ bm2,
                 const float* __restrict__ Wt, const float* __restrict__ bt,
                 const float* __restrict__ Wr, const float* __restrict__ br,
                 float* __restrict__ out)
{
    __shared__ float xs[D];
    __shared__ float hs[D];
    __shared__ float h2[D];
    __shared__ float tr[12];
    int m = blockIdx.x, t = threadIdx.x;
    xs[t] = allf[(size_t)m * D + t];
    __syncthreads();
    float s = bm1[t];
#pragma unroll 8
    for (int k = 0; k < D; k++) s = fmaf(xs[k], Wm1[(size_t)k * D + t], s);
    hs[t] = fmaxf(s, 0.f);
    __syncthreads();
    s = bm2[t];
#pragma unroll 8
    for (int k = 0; k < D; k++) s = fmaf(hs[k], Wm2[(size_t)k * D + t], s);
    h2[t] = fmaxf(s, 0.f);
    __syncthreads();
    if (t < 12) {
        const float* W = (t < 3) ? Wt : Wr;
        int N = (t < 3) ? 3 : 9;
        int n = (t < 3) ? t : (t - 3);
        float b = (t < 3) ? bt[n] : br[n];
        float s2 = b;
#pragma unroll 8
        for (int k = 0; k < D; k++) s2 = fmaf(h2[k], W[(size_t)k * N + n], s2);
        tr[t] = s2;
    }
    __syncthreads();
    if (t == 0) {
        // B = row-normalized 3x3; R = special polar factor.
        float B[3][3];
#pragma unroll
        for (int r = 0; r < 3; r++) {
            float a0 = tr[3 + r * 3 + 0], a1 = tr[3 + r * 3 + 1], a2 = tr[3 + r * 3 + 2];
            float nrm = fmaxf(sqrtf(a0 * a0 + a1 * a1 + a2 * a2), 1e-12f);
            B[r][0] = a0 / nrm; B[r][1] = a1 / nrm; B[r][2] = a2 / nrm;
        }
        float H[3][3];
#pragma unroll
        for (int r = 0; r < 3; r++)
#pragma unroll
            for (int c = 0; c < 3; c++)
                H[r][c] = B[0][r] * B[0][c] + B[1][r] * B[1][c] + B[2][r] * B[2][c];
        float V[3][3] = {{1,0,0},{0,1,0},{0,0,1}};
        for (int sweep = 0; sweep < 12; sweep++) {
            jrotf(H, V, 0, 1);
            jrotf(H, V, 0, 2);
            jrotf(H, V, 1, 2);
        }
        float l0 = H[0][0], l1 = H[1][1], l2 = H[2][2];
        int i0 = 0, i1 = 1, i2 = 2;
        if (l0 < l1) { float tl = l0; l0 = l1; l1 = tl; int ti = i0; i0 = i1; i1 = ti; }
        if (l0 < l2) { float tl = l0; l0 = l2; l2 = tl; int ti = i0; i0 = i2; i2 = ti; }
        if (l1 < l2) { float tl = l1; l1 = l2; l2 = tl; int ti = i1; i1 = i2; i2 = ti; }
        float s0 = sqrtf(fmaxf(l0, 0.f)), s1 = sqrtf(fmaxf(l1, 0.f)), s2v = sqrtf(fmaxf(l2, 0.f));
        float detB = B[0][0] * (B[1][1] * B[2][2] - B[1][2] * B[2][1])
                   - B[0][1] * (B[1][0] * B[2][2] - B[1][2] * B[2][0])
                   + B[0][2] * (B[1][0] * B[2][1] - B[1][1] * B[2][0]);
        float dsgn = (detB < 0.f) ? -1.f : 1.f;
        float inv[3];
        inv[0] = 1.f  / fmaxf(s0, 1e-12f);
        inv[1] = 1.f  / fmaxf(s1, 1e-12f);
        inv[2] = dsgn / fmaxf(s2v, 1e-12f);
        float Vs[3][3];
#pragma unroll
        for (int r = 0; r < 3; r++) { Vs[r][0] = V[r][i0]; Vs[r][1] = V[r][i1]; Vs[r][2] = V[r][i2]; }
        float T[3][3];
#pragma unroll
        for (int r = 0; r < 3; r++)
#pragma unroll
            for (int j = 0; j < 3; j++)
                T[r][j] = (B[r][0] * Vs[0][j] + B[r][1] * Vs[1][j] + B[r][2] * Vs[2][j]) * inv[j];
        float R[3][3];
#pragma unroll
        for (int r = 0; r < 3; r++)
#pragma unroll
            for (int c = 0; c < 3; c++)
                R[r][c] = T[r][0] * Vs[c][0] + T[r][1] * Vs[c][1] + T[r][2] * Vs[c][2];
        float* o = out + (size_t)m * 16;
        o[0]  = R[0][0]; o[1]  = R[0][1]; o[2]  = R[0][2]; o[3]  = tr[0];
        o[4]  = R[1][0]; o[5]  = R[1][1]; o[6]  = R[1][2]; o[7]  = tr[1];
        o[8]  = R[2][0]; o[9]  = R[2][1]; o[10] = R[2][2]; o[11] = tr[2];
        o[12] = 0.f; o[13] = 0.f; o[14] = 0.f; o[15] = 1.f;
    }
}

// ---------------- launch ----------------
extern "C" void kernel_launch(void* const* d_in, const int* in_sizes, int n_in,
                              void* d_out, int out_size)
{
    const float* feat   = (const float*)d_in[0];
    const float* W_res  = (const float*)d_in[5];
    const float* b_res  = (const float*)d_in[6];
    const float* W_cur1 = (const float*)d_in[7];
    const float* b_cur1 = (const float*)d_in[8];
    const float* W_cur2 = (const float*)d_in[9];
    const float* b_cur2 = (const float*)d_in[10];
    const float* W_tp1  = (const float*)d_in[11];
    const float* b_tp1  = (const float*)d_in[12];
    const float* W_tp2  = (const float*)d_in[13];
    const float* b_tp2  = (const float*)d_in[14];
    const float* W_fut1 = (const float*)d_in[15];
    const float* b_fut1 = (const float*)d_in[16];
    const float* W_fut2 = (const float*)d_in[17];
    const float* b_fut2 = (const float*)d_in[18];
    const float* W_m1   = (const float*)d_in[19];
    const float* b_m1   = (const float*)d_in[20];
    const float* W_m2   = (const float*)d_in[21];
    const float* b_m2   = (const float*)d_in[22];
    const float* W_t    = (const float*)d_in[23];
    const float* b_t    = (const float*)d_in[24];
    const float* W_r    = (const float*)d_in[25];
    const float* b_r    = (const float*)d_in[26];

    __nv_bfloat16 *fH, *fL, *t1H, *t1L, *t2H, *t2L, *x3H, *x3L, *wH, *wL;
    float *poolsrc, *pooled, *allf, *tf;
    cudaGetSymbolAddress((void**)&fH,  g_fH);  cudaGetSymbolAddress((void**)&fL,  g_fL);
    cudaGetSymbolAddress((void**)&t1H, g_t1H); cudaGetSymbolAddress((void**)&t1L, g_t1L);
    cudaGetSymbolAddress((void**)&t2H, g_t2H); cudaGetSymbolAddress((void**)&t2L, g_t2L);
    cudaGetSymbolAddress((void**)&x3H, g_x3H); cudaGetSymbolAddress((void**)&x3L, g_x3L);
    cudaGetSymbolAddress((void**)&wH,  g_wH);  cudaGetSymbolAddress((void**)&wL,  g_wL);
    cudaGetSymbolAddress((void**)&poolsrc, g_poolsrc);
    cudaGetSymbolAddress((void**)&pooled,  g_pooled);
    cudaGetSymbolAddress((void**)&allf,    g_allf);
    cudaGetSymbolAddress((void**)&tf,      g_tf);

    cudaFuncSetAttribute(gemm_mma, cudaFuncAttributeMaxDynamicSharedMemorySize, SMEM_TOTAL);

    // weight split + feat split + pooled zero
    wprep_kernel<<<6 * D * D / 256, 256>>>(W_res, wH, wL);
    split_kernel<<<4096, 256>>>((const float4*)feat, (__nv_bfloat162*)fH, (__nv_bfloat162*)fL,
                                (size_t)MROWS * D / 4);
    pool_zero<<<96, 512>>>(pooled);

    const size_t WS = (size_t)D * D;
    dim3 gg(4, (MROWS + 127) / 128);

    // ResConvBlock 0
    gemm_mma<<<gg, 256, SMEM_TOTAL>>>(fH, fL, wH + 0 * WS, wL + 0 * WS, b_res + 0 * D,
                                      nullptr, nullptr, nullptr, t1H, t1L, nullptr, MROWS);
    gemm_mma<<<gg, 256, SMEM_TOTAL>>>(t1H, t1L, wH + 1 * WS, wL + 1 * WS, b_res + 1 * D,
                                      nullptr, nullptr, nullptr, t2H, t2L, nullptr, MROWS);
    gemm_mma<<<gg, 256, SMEM_TOTAL>>>(t2H, t2L, wH + 2 * WS, wL + 2 * WS, b_res + 2 * D,
                                      feat, nullptr, nullptr, x3H, x3L, nullptr, MROWS);
    // ResConvBlock 1
    gemm_mma<<<gg, 256, SMEM_TOTAL>>>(x3H, x3L, wH + 3 * WS, wL + 3 * WS, b_res + 3 * D,
                                      nullptr, nullptr, nullptr, t1H, t1L, nullptr, MROWS);
    gemm_mma<<<gg, 256, SMEM_TOTAL>>>(t1H, t1L, wH + 4 * WS, wL + 4 * WS, b_res + 4 * D,
                                      nullptr, nullptr, nullptr, t2H, t2L, nullptr, MROWS);
    // last layer: fp32 output straight into pool source
    gemm_mma<<<gg, 256, SMEM_TOTAL>>>(t2H, t2L, wH + 5 * WS, wL + 5 * WS, b_res + 5 * D,
                                      nullptr, x3H, x3L, nullptr, nullptr, poolsrc, MROWS);

    // pooled mean over hw (parallel + atomic, fp32)
    pool_atomic<<<dim3(96, 8), 512>>>(poolsrc, pooled);

    // current-frame MLP -> allf[0:96]
    mlp2<<<96, 512>>>(pooled, W_cur1, b_cur1, W_cur2, b_cur2, allf, 512, 0);

    // gctx -> temporal proj -> tf; future MLP -> allf[96:192]
    tp_mlp<<<32, 512>>>(pooled, W_tp1, b_tp1, W_tp2, b_tp2, tf);
    mlp2<<<96, 512>>>(tf, W_fut1, b_fut1, W_fut2, b_fut2, allf + 96 * D, 512, 0);

    // more_mlps + pose heads + SVD + pose assembly (fused)
    head_kernel<<<NEWBN, 512>>>(allf, W_m1, b_m1, W_m2, b_m2, W_t, b_t, W_r, b_r,
                                (float*)d_out);
}